// round 4
// baseline (speedup 1.0000x reference)
#include <cuda_runtime.h>
#include <cuda_fp16.h>
#include <cstdint>
#include <cstddef>

// ----------------------------------------------------------------------------
// out[16384,4096] = spike[16384,4096] @ W[4096,4096] + bias   (fp32 I/O)
// sm_100 plain target -> legacy mma.sync.m16n8k16 HMMA.
// This round: spike matrix carried as a BITMASK (8 MB). A-fragments are
// synthesized in registers from mask bits (no A smem, no A LDSM, 16x less A
// L2/DRAM traffic). B keeps the cp.async 6-stage pipeline + LDSM4T.
// ----------------------------------------------------------------------------

static constexpr int MM = 16384, KK = 4096, NN = 4096;
static constexpr int BM = 128, BN = 256, BK = 64;
static constexpr int STAGES = 6;                 // B-only stages now
static constexpr int KTILES = KK / BK;           // 64
static constexpr int B_ST = BK * BN * 2;         // 32 KB (rows of 512 B)
static constexpr int SMEM_BYTES = STAGES * B_ST; // 192 KB
static constexpr int WPR = KK / 32;              // 128 mask words per row

__device__ __align__(128) uint32_t g_Sb[(size_t)MM * WPR]; // 8 MB spike bitmask
__device__ __align__(128) __half   g_W[(size_t)KK * NN];   // 32 MB fp16 [K,N]

// ---------------------------------------------------------------- helpers
__device__ __forceinline__ uint32_t smem_u32(const void* p) {
    uint32_t a;
    asm("{ .reg .u64 t; cvta.to.shared.u64 t, %1; cvt.u32.u64 %0, t; }"
        : "=r"(a) : "l"(p));
    return a;
}
__device__ __forceinline__ void cp16(uint32_t dst, const void* src) {
    asm volatile("cp.async.cg.shared.global [%0], [%1], 16;"
                 :: "r"(dst), "l"(src) : "memory");
}
__device__ __forceinline__ uint32_t swzB(uint32_t off) { return off ^ ((off >> 5) & 0x70); }

#define LDSM4T(R, addr)                                                         \
    asm volatile("ldmatrix.sync.aligned.m8n8.x4.trans.shared.b16 {%0,%1,%2,%3}, [%4];" \
                 : "=r"((R)[0]), "=r"((R)[1]), "=r"((R)[2]), "=r"((R)[3])       \
                 : "r"(addr))
#define MMA16816(C, A, B)                                                       \
    asm volatile("mma.sync.aligned.m16n8k16.row.col.f32.f16.f16.f32 "           \
                 "{%0,%1,%2,%3}, {%4,%5,%6,%7}, {%8,%9}, {%0,%1,%2,%3};"        \
                 : "+f"((C)[0]), "+f"((C)[1]), "+f"((C)[2]), "+f"((C)[3])       \
                 : "r"((A)[0]), "r"((A)[1]), "r"((A)[2]), "r"((A)[3]),          \
                   "r"((B)[0]), "r"((B)[1]))

// expand 2 mask bits (b0 -> low half, b1 -> high half) to fp16x2 of {0,1}
__device__ __forceinline__ uint32_t exp2b(uint32_t t) {
    return ((t & 1u) * 0x3C00u) | ((t & 2u) * 0x1E000000u);
}

// ---------------------------------------------------------------- converts
// spike fp32 -> bitmask, one 32-bit word per warp-chunk via ballot
__global__ void pack_spike(const float* __restrict__ src) {
    const int lane = threadIdx.x & 31;
    const size_t gw = ((size_t)blockIdx.x * blockDim.x + threadIdx.x) >> 5;
    const size_t nw = ((size_t)gridDim.x * blockDim.x) >> 5;
    const size_t total = (size_t)MM * WPR;
    for (size_t w = gw; w < total; w += nw) {
        const float v = src[w * 32 + lane];
        const unsigned m = __ballot_sync(0xFFFFFFFFu, v != 0.0f);
        if (lane == 0) g_Sb[w] = m;
    }
}

__global__ void cvt_w(const float4* __restrict__ src) {
    const size_t n4 = (size_t)KK * NN / 4;
    const size_t stride = (size_t)gridDim.x * blockDim.x;
    uint2* dst = reinterpret_cast<uint2*>(g_W);
    for (size_t i = (size_t)blockIdx.x * blockDim.x + threadIdx.x; i < n4; i += stride) {
        float4 v = src[i];
        __half2 a = __floats2half2_rn(v.x, v.y);
        __half2 b = __floats2half2_rn(v.z, v.w);
        uint2 p;
        p.x = *reinterpret_cast<uint32_t*>(&a);
        p.y = *reinterpret_cast<uint32_t*>(&b);
        dst[i] = p;
    }
}

// ---------------------------------------------------------------- GEMM
__global__ void __launch_bounds__(256, 1)
gemm_hmma_kernel(const float* __restrict__ bias, float* __restrict__ out) {
    extern __shared__ __align__(1024) unsigned char smem[];
    const uint32_t sb = smem_u32(smem);

    const int tid = threadIdx.x;
    const int lane = tid & 31;
    const int wid = tid >> 5;
    const int wm = wid >> 2;            // 0..1 : M half (64 rows)
    const int wn = wid & 3;             // 0..3 : N quarter (64 cols)
    const int tile_n = blockIdx.x & 15; // N fastest -> W stays L2-resident
    const int tile_m = blockIdx.x >> 4;

    const __half* Bb = g_W + tile_n * BN;
    const uint32_t* mrow0 = g_Sb + (size_t)(tile_m * BM + wm * 64 + lane) * WPR;
    const uint32_t* mrow1 = mrow0 + (size_t)32 * WPR;

    auto load_tileB = [&](int s, int t) {
        const uint32_t sB = sb + s * B_ST;
        const __half* bsrc = Bb + (size_t)(t * BK) * NN;
#pragma unroll
        for (int q = 0; q < 8; q++) {                 // 64 rows x 32 x 16B
            const int idx = tid + q * 256;
            const int r = idx >> 5, c = idx & 31;
            cp16(sB + swzB((uint32_t)(r * 512 + c * 16)), bsrc + (size_t)r * NN + c * 8);
        }
    };
    auto load_frag_b = [&](uint32_t b_regs[4][4], uint32_t sB, int kc) {
#pragma unroll
        for (int j = 0; j < 4; j++) {
            const int krow = kc * 16 + (lane & 15);
            const int colb = (wn * 64 + j * 16 + (lane >> 4) * 8) * 2;
            LDSM4T(b_regs[j], sB + swzB((uint32_t)(krow * 512 + colb)));
        }
    };

    // -------- prologue
#pragma unroll
    for (int s = 0; s < STAGES - 1; s++) {
        load_tileB(s, s);
        asm volatile("cp.async.commit_group;");
    }
    uint2 cur0 = *reinterpret_cast<const uint2*>(mrow0 + 0);   // masks for t=0
    uint2 cur1 = *reinterpret_cast<const uint2*>(mrow1 + 0);
    uint2 nxt0 = *reinterpret_cast<const uint2*>(mrow0 + 2);   // masks for t=1
    uint2 nxt1 = *reinterpret_cast<const uint2*>(mrow1 + 2);

    float acc[4][8][4];
#pragma unroll
    for (int i = 0; i < 4; i++)
#pragma unroll
        for (int j = 0; j < 8; j++)
#pragma unroll
            for (int q = 0; q < 4; q++) acc[i][j][q] = 0.0f;

    uint32_t B2[2][4][4];
    asm volatile("cp.async.wait_group %0;" :: "n"(STAGES - 2));
    __syncthreads();
    load_frag_b(B2[0], sb, 0);

    const int c2 = (lane & 3) * 2;      // column-bit offset within 16-bit window

#pragma unroll 1
    for (int t = 0; t < KTILES; t++) {
        const uint32_t sB = sb + (t % STAGES) * B_ST;

        // distribute this K-tile's 64-bit row masks to the owning threads
        uint32_t M0x[4], M0y[4], M1x[4], M1y[4];
#pragma unroll
        for (int i = 0; i < 4; i++) {
            const int r0 = (i & 1) * 16 + (lane >> 2);  // row within the uint2 set
            const int r1 = r0 + 8;
            const uint2 s2 = (i < 2) ? cur0 : cur1;
            M0x[i] = __shfl_sync(0xFFFFFFFFu, s2.x, r0);
            M0y[i] = __shfl_sync(0xFFFFFFFFu, s2.y, r0);
            M1x[i] = __shfl_sync(0xFFFFFFFFu, s2.x, r1);
            M1y[i] = __shfl_sync(0xFFFFFFFFu, s2.y, r1);
        }

#pragma unroll
        for (int kc = 0; kc < 4; kc++) {
            const int cur = kc & 1;
            const int nxtb = cur ^ 1;
            if (kc == 3) {
                if (t + 1 < KTILES) {
                    asm volatile("cp.async.wait_group %0;" :: "n"(STAGES - 2));
                    __syncthreads();
                    load_frag_b(B2[nxtb], sb + ((t + 1) % STAGES) * B_ST, 0);
                }
            } else {
                load_frag_b(B2[nxtb], sB, kc + 1);
            }

            const int sh = (kc & 1) * 16 + c2;
#pragma unroll
            for (int i = 0; i < 4; i++) {
                const uint32_t m0 = (kc < 2) ? M0x[i] : M0y[i];
                const uint32_t m1 = (kc < 2) ? M1x[i] : M1y[i];
                const uint32_t t0 = m0 >> sh;
                const uint32_t t1 = m1 >> sh;
                uint32_t a[4];
                a[0] = exp2b(t0);          // row g,   k lo8
                a[1] = exp2b(t1);          // row g+8, k lo8
                a[2] = exp2b(t0 >> 8);     // row g,   k hi8
                a[3] = exp2b(t1 >> 8);     // row g+8, k hi8
#pragma unroll
                for (int jj = 0; jj < 8; jj++)
                    MMA16816(acc[i][jj], a, B2[cur][jj >> 1] + (jj & 1) * 2);
            }

            if (kc == 0) {
                if (t + STAGES - 1 < KTILES) load_tileB((t + STAGES - 1) % STAGES, t + STAGES - 1);
                asm volatile("cp.async.commit_group;");
            }
        }

        // rotate mask double-buffer, prefetch t+2 (L2-resident, 8 MB total)
        cur0 = nxt0; cur1 = nxt1;
        if (t + 2 < KTILES) {
            nxt0 = *reinterpret_cast<const uint2*>(mrow0 + (t + 2) * 2);
            nxt1 = *reinterpret_cast<const uint2*>(mrow1 + (t + 2) * 2);
        }
    }
    asm volatile("cp.async.wait_all;");

    // -------- epilogue: direct fp32 stores + bias
    float2 bv[8];
#pragma unroll
    for (int jj = 0; jj < 8; jj++)
        bv[jj] = *reinterpret_cast<const float2*>(
            bias + tile_n * 256 + wn * 64 + jj * 8 + (lane & 3) * 2);

#pragma unroll
    for (int i = 0; i < 4; i++) {
        const int r = tile_m * 128 + wm * 64 + i * 16 + (lane >> 2);
        float* o0 = out + (size_t)r * NN + tile_n * 256 + wn * 64 + (lane & 3) * 2;
        float* o1 = o0 + (size_t)8 * NN;
#pragma unroll
        for (int jj = 0; jj < 8; jj++) {
            float2 v0 = { acc[i][jj][0] + bv[jj].x, acc[i][jj][1] + bv[jj].y };
            float2 v1 = { acc[i][jj][2] + bv[jj].x, acc[i][jj][3] + bv[jj].y };
            *reinterpret_cast<float2*>(o0 + jj * 8) = v0;
            *reinterpret_cast<float2*>(o1 + jj * 8) = v1;
        }
    }
}

// ---------------------------------------------------------------- launch
extern "C" void kernel_launch(void* const* d_in, const int* in_sizes, int n_in,
                              void* d_out, int out_size) {
    const float* sparse = (const float*)d_in[0];
    const float* weight = (const float*)d_in[1];
    const float* bias   = (const float*)d_in[2];
    float* out = (float*)d_out;

    cudaFuncSetAttribute(gemm_hmma_kernel,
                         cudaFuncAttributeMaxDynamicSharedMemorySize, SMEM_BYTES);

    pack_spike<<<2048, 256>>>(sparse);
    cvt_w<<<2048, 256>>>(reinterpret_cast<const float4*>(weight));
    gemm_hmma_kernel<<<(MM / BM) * (NN / BN), 256, SMEM_BYTES>>>(bias, out);
}